// round 3
// baseline (speedup 1.0000x reference)
#include <cuda_runtime.h>

#define NN 100000
#define EE 1600000
#define HH 128
#define OUTC 40

// ---------------- static device scratch (allocation-free rule) ----------------
__device__ float g_h [(size_t)NN * HH];   // xW (layer1 then layer2)
__device__ float g_x1[(size_t)NN * HH];   // relu(bn1(gcn1))
__device__ float g_x2[(size_t)NN * HH];   // relu(bn2(gcn2))
__device__ float g_dinv[NN];
__device__ int   g_deg[NN];
__device__ int   g_rowptr[NN + 1];
__device__ int   g_cursor[NN];
__device__ int   g_cols[EE];
__device__ int   g_bsum[128];

// ---------------- CSR build ----------------
__global__ void zero_deg(int n) {
    int i = blockIdx.x * blockDim.x + threadIdx.x;
    if (i < n) g_deg[i] = 0;
}

__global__ void histo(const int* __restrict__ rows, int e) {
    int i = blockIdx.x * blockDim.x + threadIdx.x;
    if (i < e) atomicAdd(&g_deg[rows[i]], 1);
}

__global__ void calc_dinv(int n) {
    int i = blockIdx.x * blockDim.x + threadIdx.x;
    if (i < n) g_dinv[i] = rsqrtf((float)g_deg[i] + 1.0f);
}

__global__ void scan_local(int n) {
    __shared__ int s[1024];
    int i = blockIdx.x * 1024 + threadIdx.x;
    int v = (i < n) ? g_deg[i] : 0;
    s[threadIdx.x] = v;
    __syncthreads();
    for (int off = 1; off < 1024; off <<= 1) {
        int t = (threadIdx.x >= off) ? s[threadIdx.x - off] : 0;
        __syncthreads();
        s[threadIdx.x] += t;
        __syncthreads();
    }
    if (i < n) g_rowptr[i] = s[threadIdx.x] - v;   // exclusive within block
    if (threadIdx.x == 1023) g_bsum[blockIdx.x] = s[1023];
}

__global__ void scan_sums(int nb) {
    if (threadIdx.x == 0 && blockIdx.x == 0) {
        int acc = 0;
        for (int b = 0; b < nb; b++) { int t = g_bsum[b]; g_bsum[b] = acc; acc += t; }
    }
}

__global__ void add_off(int n, int e) {
    int i = blockIdx.x * blockDim.x + threadIdx.x;
    if (i < n) {
        int v = g_rowptr[i] + g_bsum[i >> 10];
        g_rowptr[i] = v;
        g_cursor[i] = v;
    }
    if (i == 0) g_rowptr[n] = e;
}

__global__ void scatter_edges(const int* __restrict__ rows, const int* __restrict__ cols, int e) {
    int i = blockIdx.x * blockDim.x + threadIdx.x;
    if (i < e) {
        int r = rows[i];
        int p = atomicAdd(&g_cursor[r], 1);
        g_cols[p] = cols[i];
    }
}

// ---------------- SGEMM: C[M,128] = A[M,128] @ B[128,128] ----------------
// BM=128, BN=128, BK=16, 256 threads, 8x8 register tile
__global__ void sgemm128(int a_sel, const float* __restrict__ Aext,
                         const float* __restrict__ B, int M) {
    const float* __restrict__ A = (a_sel == 0) ? Aext : g_x1;
    float* __restrict__ C = g_h;

    __shared__ float As[16][128];
    __shared__ float Bs[16][128];

    int tid = threadIdx.x;
    int bm  = blockIdx.x * 128;
    int tx  = tid & 15;      // n-group
    int ty  = tid >> 4;      // m-group

    float acc[8][8];
#pragma unroll
    for (int i = 0; i < 8; i++)
#pragma unroll
        for (int j = 0; j < 8; j++) acc[i][j] = 0.0f;

    int a_m = tid >> 2;            // 0..63
    int a_k = (tid & 3) << 2;      // 0,4,8,12
    int b_k = tid >> 5;            // 0..7
    int b_n = (tid & 31) << 2;     // 0..124

    for (int k0 = 0; k0 < 128; k0 += 16) {
#pragma unroll
        for (int h2 = 0; h2 < 2; h2++) {
            int m  = a_m + h2 * 64;
            int gm = bm + m;
            if (gm >= M) gm = M - 1;            // clamp loads, stores are masked
            float4 v = *(const float4*)&A[(size_t)gm * 128 + k0 + a_k];
            As[a_k + 0][m] = v.x;
            As[a_k + 1][m] = v.y;
            As[a_k + 2][m] = v.z;
            As[a_k + 3][m] = v.w;
        }
#pragma unroll
        for (int h2 = 0; h2 < 2; h2++) {
            int k = b_k + h2 * 8;
            *(float4*)&Bs[k][b_n] = *(const float4*)&B[(size_t)(k0 + k) * 128 + b_n];
        }
        __syncthreads();
#pragma unroll
        for (int k = 0; k < 16; k++) {
            float a[8], b[8];
            *(float4*)(a)     = *(const float4*)&As[k][ty * 8];
            *(float4*)(a + 4) = *(const float4*)&As[k][ty * 8 + 4];
            *(float4*)(b)     = *(const float4*)&Bs[k][tx * 8];
            *(float4*)(b + 4) = *(const float4*)&Bs[k][tx * 8 + 4];
#pragma unroll
            for (int i = 0; i < 8; i++)
#pragma unroll
                for (int j = 0; j < 8; j++)
                    acc[i][j] = fmaf(a[i], b[j], acc[i][j]);
        }
        __syncthreads();
    }
#pragma unroll
    for (int i = 0; i < 8; i++) {
        int gm = bm + ty * 8 + i;
        if (gm < M) {
            *(float4*)&C[(size_t)gm * 128 + tx * 8]     =
                make_float4(acc[i][0], acc[i][1], acc[i][2], acc[i][3]);
            *(float4*)&C[(size_t)gm * 128 + tx * 8 + 4] =
                make_float4(acc[i][4], acc[i][5], acc[i][6], acc[i][7]);
        }
    }
}

// ---------------- gather aggregation + bias + BN + ReLU ----------------
// one warp per destination node; lane covers 4 channels
__global__ void aggregate(const float* __restrict__ bias,
                          const float* __restrict__ gamma,
                          const float* __restrict__ beta,
                          const float* __restrict__ mean,
                          const float* __restrict__ var,
                          int dst_sel, int n) {
    int gw = (blockIdx.x * blockDim.x + threadIdx.x) >> 5;
    if (gw >= n) return;
    int lane = threadIdx.x & 31;
    int c0   = lane << 2;

    float di    = g_dinv[gw];
    int   start = g_rowptr[gw];
    int   end   = g_rowptr[gw + 1];

    float ax = 0.f, ay = 0.f, az = 0.f, aw = 0.f;
    int j = start;
    for (; j + 1 < end; j += 2) {
        int c1 = g_cols[j], c2 = g_cols[j + 1];
        float w1 = di * g_dinv[c1];
        float w2 = di * g_dinv[c2];
        float4 v1 = *(const float4*)&g_h[(size_t)c1 * 128 + c0];
        float4 v2 = *(const float4*)&g_h[(size_t)c2 * 128 + c0];
        ax += v1.x * w1 + v2.x * w2;
        ay += v1.y * w1 + v2.y * w2;
        az += v1.z * w1 + v2.z * w2;
        aw += v1.w * w1 + v2.w * w2;
    }
    if (j < end) {
        int c1 = g_cols[j];
        float w1 = di * g_dinv[c1];
        float4 v1 = *(const float4*)&g_h[(size_t)c1 * 128 + c0];
        ax += v1.x * w1; ay += v1.y * w1; az += v1.z * w1; aw += v1.w * w1;
    }
    // self-loop
    {
        float ws = di * di;
        float4 hs = *(const float4*)&g_h[(size_t)gw * 128 + c0];
        ax += hs.x * ws; ay += hs.y * ws; az += hs.z * ws; aw += hs.w * ws;
    }
    // epilogue: (agg + b - mean) * gamma*rsqrt(var+eps) + beta, then relu
    float4 bb = *(const float4*)&bias[c0];
    float4 gg = *(const float4*)&gamma[c0];
    float4 be = *(const float4*)&beta[c0];
    float4 mm = *(const float4*)&mean[c0];
    float4 vv = *(const float4*)&var[c0];

    float s0 = gg.x * rsqrtf(vv.x + 1e-5f);
    float s1 = gg.y * rsqrtf(vv.y + 1e-5f);
    float s2 = gg.z * rsqrtf(vv.z + 1e-5f);
    float s3 = gg.w * rsqrtf(vv.w + 1e-5f);

    float y0 = fmaxf((ax + bb.x - mm.x) * s0 + be.x, 0.0f);
    float y1 = fmaxf((ay + bb.y - mm.y) * s1 + be.y, 0.0f);
    float y2 = fmaxf((az + bb.z - mm.z) * s2 + be.z, 0.0f);
    float y3 = fmaxf((aw + bb.w - mm.w) * s3 + be.w, 0.0f);

    float* __restrict__ out = (dst_sel == 1) ? g_x1 : g_x2;
    *(float4*)&out[(size_t)gw * 128 + c0] = make_float4(y0, y1, y2, y3);
}

// ---------------- final FC: out = [x0 | x1 | x2] @ fc_W + fc_b ----------------
// block: 160 threads = 32 rows x 5 col-groups (8 cols each). K = 3 x 128.
__global__ void fc_kernel(const float* __restrict__ x0,
                          const float* __restrict__ W,   // [384, 40] row-major
                          const float* __restrict__ bias,
                          float* __restrict__ out, int n) {
    __shared__ float Ws[128 * 40];   // 20 KB: one 128-row chunk of fc_W
    __shared__ float St[32 * 130];   // 16.25 KB: 32-row input tile, padded stride

    int tid = threadIdx.x;           // 0..159
    int r   = tid / 5;               // 0..31
    int cg  = (tid % 5) * 8;         // 0,8,16,24,32
    int row = blockIdx.x * 32 + r;

    float acc[8];
#pragma unroll
    for (int q = 0; q < 8; q++) acc[q] = bias[cg + q];

    for (int s = 0; s < 3; s++) {
        const float* __restrict__ S = (s == 0) ? x0 : ((s == 1) ? g_x1 : g_x2);
        __syncthreads();
        // stage W chunk [128,40] for this source
        for (int i = tid; i < 1280; i += 160)
            ((float4*)Ws)[i] = ((const float4*)W)[s * 1280 + i];
        // stage input tile [32,128] with padded stride 130 (bank-conflict-free)
        for (int i = tid; i < 1024; i += 160) {
            int rr = i >> 5;
            int kk = (i & 31) << 2;
            int gr = blockIdx.x * 32 + rr;
            float4 v = (gr < n) ? *(const float4*)&S[(size_t)gr * 128 + kk]
                                : make_float4(0.f, 0.f, 0.f, 0.f);
            St[rr * 130 + kk + 0] = v.x;
            St[rr * 130 + kk + 1] = v.y;
            St[rr * 130 + kk + 2] = v.z;
            St[rr * 130 + kk + 3] = v.w;
        }
        __syncthreads();
#pragma unroll 4
        for (int k = 0; k < 128; k++) {
            float a = St[r * 130 + k];
            const float* wr = &Ws[k * 40 + cg];
            float4 w0 = *(const float4*)(wr);
            float4 w1 = *(const float4*)(wr + 4);
            acc[0] = fmaf(a, w0.x, acc[0]);
            acc[1] = fmaf(a, w0.y, acc[1]);
            acc[2] = fmaf(a, w0.z, acc[2]);
            acc[3] = fmaf(a, w0.w, acc[3]);
            acc[4] = fmaf(a, w1.x, acc[4]);
            acc[5] = fmaf(a, w1.y, acc[5]);
            acc[6] = fmaf(a, w1.z, acc[6]);
            acc[7] = fmaf(a, w1.w, acc[7]);
        }
    }
    if (row < n) {
        *(float4*)&out[(size_t)row * 40 + cg]     = make_float4(acc[0], acc[1], acc[2], acc[3]);
        *(float4*)&out[(size_t)row * 40 + cg + 4] = make_float4(acc[4], acc[5], acc[6], acc[7]);
    }
}

// ---------------- launch ----------------
extern "C" void kernel_launch(void* const* d_in, const int* in_sizes, int n_in,
                              void* d_out, int out_size) {
    const float* x   = (const float*)d_in[0];
    const int*   ei  = (const int*)  d_in[1];
    const float* W1  = (const float*)d_in[2];
    const float* b1  = (const float*)d_in[3];
    const float* W2  = (const float*)d_in[4];
    const float* b2  = (const float*)d_in[5];
    const float* g1  = (const float*)d_in[6];
    const float* be1 = (const float*)d_in[7];
    const float* m1  = (const float*)d_in[8];
    const float* v1  = (const float*)d_in[9];
    const float* g2  = (const float*)d_in[10];
    const float* be2 = (const float*)d_in[11];
    const float* m2  = (const float*)d_in[12];
    const float* v2  = (const float*)d_in[13];
    const float* fcW = (const float*)d_in[14];
    const float* fcb = (const float*)d_in[15];
    float* out = (float*)d_out;

    int N = in_sizes[0] / 128;
    int E = in_sizes[1] / 2;
    const int* rows = ei;
    const int* cols = ei + E;

    const int T = 256;
    // CSR build (pull-based aggregation needs edges grouped by destination row)
    zero_deg<<<(N + T - 1) / T, T>>>(N);
    histo<<<(E + T - 1) / T, T>>>(rows, E);
    calc_dinv<<<(N + T - 1) / T, T>>>(N);
    int nb = (N + 1023) / 1024;
    scan_local<<<nb, 1024>>>(N);
    scan_sums<<<1, 32>>>(nb);
    add_off<<<(N + T - 1) / T, T>>>(N, E);
    scatter_edges<<<(E + T - 1) / T, T>>>(rows, cols, E);

    int gblocks = (N + 127) / 128;
    // layer 1
    sgemm128<<<gblocks, 256>>>(0, x, W1, N);
    aggregate<<<(N + 7) / 8, 256>>>(b1, g1, be1, m1, v1, 1, N);
    // layer 2
    sgemm128<<<gblocks, 256>>>(1, x, W2, N);
    aggregate<<<(N + 7) / 8, 256>>>(b2, g2, be2, m2, v2, 2, N);
    // final FC on concat
    fc_kernel<<<(N + 31) / 32, 160>>>(x, fcW, fcb, out, N);
}

// round 4
// speedup vs baseline: 1.0029x; 1.0029x over previous
#include <cuda_runtime.h>

#define NN 100000
#define EE 1600000
#define HH 128
#define OUTC 40

typedef unsigned long long u64;

// ---------------- static device scratch (allocation-free rule) ----------------
__device__ float g_h [(size_t)NN * HH];   // xW (layer1 then layer2)
__device__ float g_x1[(size_t)NN * HH];   // relu(bn1(gcn1))
__device__ float g_x2[(size_t)NN * HH];   // relu(bn2(gcn2))
__device__ float g_dinv[NN];
__device__ int   g_deg[NN];
__device__ int   g_rowptr[NN + 1];
__device__ int   g_cursor[NN];
__device__ int   g_cols[EE];
__device__ float g_wgt[EE];
__device__ int   g_bsum[128];

// ---------------- f32x2 helpers (FFMA2 — only reachable via PTX) ----------------
__device__ __forceinline__ u64 pack2_dup(float v) {
    u64 r; asm("mov.b64 %0, {%1, %1};" : "=l"(r) : "f"(v)); return r;
}
__device__ __forceinline__ void ffma2(u64 &d, u64 a, u64 b) {
    asm("fma.rn.f32x2 %0, %1, %2, %0;" : "+l"(d) : "l"(a), "l"(b));
}

// ---------------- CSR build ----------------
__global__ void zero_deg(int n) {
    int i = blockIdx.x * blockDim.x + threadIdx.x;
    if (i < n) g_deg[i] = 0;
}

__global__ void histo(const int* __restrict__ rows, int e) {
    int i = blockIdx.x * blockDim.x + threadIdx.x;
    if (i < e) atomicAdd(&g_deg[rows[i]], 1);
}

__global__ void scan_local(int n) {
    __shared__ int s[1024];
    int i = blockIdx.x * 1024 + threadIdx.x;
    int v = (i < n) ? g_deg[i] : 0;
    s[threadIdx.x] = v;
    __syncthreads();
    for (int off = 1; off < 1024; off <<= 1) {
        int t = (threadIdx.x >= off) ? s[threadIdx.x - off] : 0;
        __syncthreads();
        s[threadIdx.x] += t;
        __syncthreads();
    }
    if (i < n) g_rowptr[i] = s[threadIdx.x] - v;   // exclusive within block
    if (threadIdx.x == 1023) g_bsum[blockIdx.x] = s[1023];
}

// parallel exclusive scan of block sums (nb <= 128)
__global__ void scan_sums(int nb) {
    __shared__ int s[128];
    int t = threadIdx.x;
    int v = (t < nb) ? g_bsum[t] : 0;
    s[t] = v;
    __syncthreads();
    for (int off = 1; off < 128; off <<= 1) {
        int u = (t >= off) ? s[t - off] : 0;
        __syncthreads();
        s[t] += u;
        __syncthreads();
    }
    if (t < nb) g_bsum[t] = s[t] - v;  // exclusive
}

__global__ void add_off(int n, int e) {
    int i = blockIdx.x * blockDim.x + threadIdx.x;
    if (i < n) {
        int v = g_rowptr[i] + g_bsum[i >> 10];
        g_rowptr[i] = v;
        g_cursor[i] = v;
        g_dinv[i]   = rsqrtf((float)g_deg[i] + 1.0f);
    }
    if (i == 0) g_rowptr[n] = e;
}

__global__ void scatter_edges(const int* __restrict__ rows, const int* __restrict__ cols, int e) {
    int i = blockIdx.x * blockDim.x + threadIdx.x;
    if (i < e) {
        int r = rows[i];
        int c = cols[i];
        int p = atomicAdd(&g_cursor[r], 1);
        g_cols[p] = c;
        g_wgt[p]  = g_dinv[r] * g_dinv[c];
    }
}

// ---------------- SGEMM: C[M,128] = A[M,128] @ B[128,128], f32x2 inner ----------------
// BM=128, BN=128, BK=16, 256 threads, 8(m) x 4(f32x2 n-pairs) register tile
__global__ __launch_bounds__(256) void sgemm128(int a_sel, const float* __restrict__ Aext,
                                                const float* __restrict__ B, int M) {
    const float* __restrict__ A = (a_sel == 0) ? Aext : g_x1;
    float* __restrict__ C = g_h;

    __shared__ float As[16][128];
    __shared__ float Bs[16][128];

    int tid = threadIdx.x;
    int bm  = blockIdx.x * 128;
    int tx  = tid & 15;      // n-group (8 floats = 4 pairs)
    int ty  = tid >> 4;      // m-group

    u64 acc[8][4];
#pragma unroll
    for (int i = 0; i < 8; i++)
#pragma unroll
        for (int j = 0; j < 4; j++) acc[i][j] = 0ull;

    int a_m = tid >> 2;            // 0..63
    int a_k = (tid & 3) << 2;      // 0,4,8,12
    int b_k = tid >> 5;            // 0..7
    int b_n = (tid & 31) << 2;     // 0..124

    for (int k0 = 0; k0 < 128; k0 += 16) {
#pragma unroll
        for (int h2 = 0; h2 < 2; h2++) {
            int m  = a_m + h2 * 64;
            int gm = bm + m;
            if (gm >= M) gm = M - 1;            // clamp loads, stores are masked
            float4 v = *(const float4*)&A[(size_t)gm * 128 + k0 + a_k];
            As[a_k + 0][m] = v.x;
            As[a_k + 1][m] = v.y;
            As[a_k + 2][m] = v.z;
            As[a_k + 3][m] = v.w;
        }
#pragma unroll
        for (int h2 = 0; h2 < 2; h2++) {
            int k = b_k + h2 * 8;
            *(float4*)&Bs[k][b_n] = *(const float4*)&B[(size_t)(k0 + k) * 128 + b_n];
        }
        __syncthreads();
#pragma unroll
        for (int k = 0; k < 16; k++) {
            float a[8];
            *(float4*)(a)     = *(const float4*)&As[k][ty * 8];
            *(float4*)(a + 4) = *(const float4*)&As[k][ty * 8 + 4];
            ulonglong2 bl = *(const ulonglong2*)&Bs[k][tx * 8];      // (b0,b1),(b2,b3)
            ulonglong2 bh = *(const ulonglong2*)&Bs[k][tx * 8 + 4];  // (b4,b5),(b6,b7)
            u64 a2[8];
#pragma unroll
            for (int i = 0; i < 8; i++) a2[i] = pack2_dup(a[i]);
#pragma unroll
            for (int i = 0; i < 8; i++) {
                ffma2(acc[i][0], a2[i], bl.x);
                ffma2(acc[i][1], a2[i], bl.y);
                ffma2(acc[i][2], a2[i], bh.x);
                ffma2(acc[i][3], a2[i], bh.y);
            }
        }
        __syncthreads();
    }
#pragma unroll
    for (int i = 0; i < 8; i++) {
        int gm = bm + ty * 8 + i;
        if (gm < M) {
            *(ulonglong2*)&C[(size_t)gm * 128 + tx * 8]     = make_ulonglong2(acc[i][0], acc[i][1]);
            *(ulonglong2*)&C[(size_t)gm * 128 + tx * 8 + 4] = make_ulonglong2(acc[i][2], acc[i][3]);
        }
    }
}

// ---------------- gather aggregation + bias + BN + ReLU ----------------
// one warp per destination node; lane covers 4 channels; unroll x4 for MLP
__global__ void aggregate(const float* __restrict__ bias,
                          const float* __restrict__ gamma,
                          const float* __restrict__ beta,
                          const float* __restrict__ mean,
                          const float* __restrict__ var,
                          int dst_sel, int n) {
    int gw = (blockIdx.x * blockDim.x + threadIdx.x) >> 5;
    if (gw >= n) return;
    int lane = threadIdx.x & 31;
    int c0   = lane << 2;

    float di    = g_dinv[gw];
    int   start = g_rowptr[gw];
    int   end   = g_rowptr[gw + 1];

    float ax = 0.f, ay = 0.f, az = 0.f, aw = 0.f;
    int j = start;
    for (; j + 3 < end; j += 4) {
        int   c1 = g_cols[j],     c2 = g_cols[j + 1];
        int   c3 = g_cols[j + 2], c4 = g_cols[j + 3];
        float w1 = g_wgt[j],      w2 = g_wgt[j + 1];
        float w3 = g_wgt[j + 2],  w4 = g_wgt[j + 3];
        float4 v1 = *(const float4*)&g_h[(size_t)c1 * 128 + c0];
        float4 v2 = *(const float4*)&g_h[(size_t)c2 * 128 + c0];
        float4 v3 = *(const float4*)&g_h[(size_t)c3 * 128 + c0];
        float4 v4 = *(const float4*)&g_h[(size_t)c4 * 128 + c0];
        ax += v1.x * w1 + v2.x * w2 + v3.x * w3 + v4.x * w4;
        ay += v1.y * w1 + v2.y * w2 + v3.y * w3 + v4.y * w4;
        az += v1.z * w1 + v2.z * w2 + v3.z * w3 + v4.z * w4;
        aw += v1.w * w1 + v2.w * w2 + v3.w * w3 + v4.w * w4;
    }
    for (; j < end; j++) {
        int c1 = g_cols[j];
        float w1 = g_wgt[j];
        float4 v1 = *(const float4*)&g_h[(size_t)c1 * 128 + c0];
        ax += v1.x * w1; ay += v1.y * w1; az += v1.z * w1; aw += v1.w * w1;
    }
    // self-loop
    {
        float ws = di * di;
        float4 hs = *(const float4*)&g_h[(size_t)gw * 128 + c0];
        ax += hs.x * ws; ay += hs.y * ws; az += hs.z * ws; aw += hs.w * ws;
    }
    // epilogue: (agg + b - mean) * gamma*rsqrt(var+eps) + beta, then relu
    float4 bb = *(const float4*)&bias[c0];
    float4 gg = *(const float4*)&gamma[c0];
    float4 be = *(const float4*)&beta[c0];
    float4 mm = *(const float4*)&mean[c0];
    float4 vv = *(const float4*)&var[c0];

    float s0 = gg.x * rsqrtf(vv.x + 1e-5f);
    float s1 = gg.y * rsqrtf(vv.y + 1e-5f);
    float s2 = gg.z * rsqrtf(vv.z + 1e-5f);
    float s3 = gg.w * rsqrtf(vv.w + 1e-5f);

    float y0 = fmaxf((ax + bb.x - mm.x) * s0 + be.x, 0.0f);
    float y1 = fmaxf((ay + bb.y - mm.y) * s1 + be.y, 0.0f);
    float y2 = fmaxf((az + bb.z - mm.z) * s2 + be.z, 0.0f);
    float y3 = fmaxf((aw + bb.w - mm.w) * s3 + be.w, 0.0f);

    float* __restrict__ out = (dst_sel == 1) ? g_x1 : g_x2;
    *(float4*)&out[(size_t)gw * 128 + c0] = make_float4(y0, y1, y2, y3);
}

// ---------------- final FC: out = [x0 | x1 | x2] @ fc_W + fc_b, f32x2 inner ----------------
// block: 160 threads = 32 rows x 5 col-groups (8 cols = 4 pairs each). K = 3 x 128.
__global__ void fc_kernel(const float* __restrict__ x0,
                          const float* __restrict__ W,   // [384, 40] row-major
                          const float* __restrict__ bias,
                          float* __restrict__ out, int n) {
    __shared__ float Ws[128 * 40];   // 20 KB: one 128-row chunk of fc_W
    __shared__ float St[32 * 130];   // 16.25 KB: 32-row input tile, padded stride

    int tid = threadIdx.x;           // 0..159
    int r   = tid / 5;               // 0..31
    int cg  = (tid % 5) * 8;         // 0,8,16,24,32
    int row = blockIdx.x * 32 + r;

    u64 acc[4];
    {
        ulonglong2 b0 = *(const ulonglong2*)&bias[cg];
        ulonglong2 b1 = *(const ulonglong2*)&bias[cg + 4];
        acc[0] = b0.x; acc[1] = b0.y; acc[2] = b1.x; acc[3] = b1.y;
    }

    for (int s = 0; s < 3; s++) {
        const float* __restrict__ S = (s == 0) ? x0 : ((s == 1) ? g_x1 : g_x2);
        __syncthreads();
        // stage W chunk [128,40] for this source
        for (int i = tid; i < 1280; i += 160)
            ((float4*)Ws)[i] = ((const float4*)W)[s * 1280 + i];
        // stage input tile [32,128] with padded stride 130 (bank-conflict-free)
        for (int i = tid; i < 1024; i += 160) {
            int rr = i >> 5;
            int kk = (i & 31) << 2;
            int gr = blockIdx.x * 32 + rr;
            float4 v = (gr < n) ? *(const float4*)&S[(size_t)gr * 128 + kk]
                                : make_float4(0.f, 0.f, 0.f, 0.f);
            St[rr * 130 + kk + 0] = v.x;
            St[rr * 130 + kk + 1] = v.y;
            St[rr * 130 + kk + 2] = v.z;
            St[rr * 130 + kk + 3] = v.w;
        }
        __syncthreads();
#pragma unroll 4
        for (int k = 0; k < 128; k++) {
            u64 a2 = pack2_dup(St[r * 130 + k]);
            const float* wr = &Ws[k * 40 + cg];
            ulonglong2 w0 = *(const ulonglong2*)(wr);
            ulonglong2 w1 = *(const ulonglong2*)(wr + 4);
            ffma2(acc[0], a2, w0.x);
            ffma2(acc[1], a2, w0.y);
            ffma2(acc[2], a2, w1.x);
            ffma2(acc[3], a2, w1.y);
        }
    }
    if (row < n) {
        *(ulonglong2*)&out[(size_t)row * 40 + cg]     = make_ulonglong2(acc[0], acc[1]);
        *(ulonglong2*)&out[(size_t)row * 40 + cg + 4] = make_ulonglong2(acc[2], acc[3]);
    }
}

// ---------------- launch ----------------
extern "C" void kernel_launch(void* const* d_in, const int* in_sizes, int n_in,
                              void* d_out, int out_size) {
    const float* x   = (const float*)d_in[0];
    const int*   ei  = (const int*)  d_in[1];
    const float* W1  = (const float*)d_in[2];
    const float* b1  = (const float*)d_in[3];
    const float* W2  = (const float*)d_in[4];
    const float* b2  = (const float*)d_in[5];
    const float* g1  = (const float*)d_in[6];
    const float* be1 = (const float*)d_in[7];
    const float* m1  = (const float*)d_in[8];
    const float* v1  = (const float*)d_in[9];
    const float* g2  = (const float*)d_in[10];
    const float* be2 = (const float*)d_in[11];
    const float* m2  = (const float*)d_in[12];
    const float* v2  = (const float*)d_in[13];
    const float* fcW = (const float*)d_in[14];
    const float* fcb = (const float*)d_in[15];
    float* out = (float*)d_out;

    int N = in_sizes[0] / 128;
    int E = in_sizes[1] / 2;
    const int* rows = ei;
    const int* cols = ei + E;

    const int T = 256;
    // CSR build (pull-based aggregation needs edges grouped by destination row)
    zero_deg<<<(N + T - 1) / T, T>>>(N);
    histo<<<(E + T - 1) / T, T>>>(rows, E);
    int nb = (N + 1023) / 1024;
    scan_local<<<nb, 1024>>>(N);
    scan_sums<<<1, 128>>>(nb);
    add_off<<<(N + T - 1) / T, T>>>(N, E);
    scatter_edges<<<(E + T - 1) / T, T>>>(rows, cols, E);

    int gblocks = (N + 127) / 128;
    // layer 1
    sgemm128<<<gblocks, 256>>>(0, x, W1, N);
    aggregate<<<(N + 7) / 8, 256>>>(b1, g1, be1, m1, v1, 1, N);
    // layer 2
    sgemm128<<<gblocks, 256>>>(1, x, W2, N);
    aggregate<<<(N + 7) / 8, 256>>>(b2, g2, be2, m2, v2, 2, N);
    // final FC on concat
    fc_kernel<<<(N + 31) / 32, 160>>>(x, fcW, fcb, out, N);
}

// round 5
// speedup vs baseline: 1.0909x; 1.0877x over previous
#include <cuda_runtime.h>
#include <cuda_fp16.h>

#define NN 100000
#define EE 1600000
#define HH 128
#define OUTC 40

typedef unsigned long long u64;

// ---------------- static device scratch (allocation-free rule) ----------------
__device__ __half g_h [(size_t)NN * HH];  // xW (layer1 then layer2), fp16 storage
__device__ float  g_x1[(size_t)NN * HH];  // relu(bn1(gcn1))
__device__ float  g_x2[(size_t)NN * HH];  // relu(bn2(gcn2))
__device__ float  g_dinv[NN];
__device__ int    g_deg[NN];
__device__ int    g_rowptr[NN + 1];
__device__ int    g_cursor[NN];
__device__ int    g_cols[EE];
__device__ float  g_wgt[EE];
__device__ int    g_bsum[128];

// ---------------- f32x2 helpers (FFMA2 — only reachable via PTX) ----------------
__device__ __forceinline__ u64 pack2_dup(float v) {
    u64 r; asm("mov.b64 %0, {%1, %1};" : "=l"(r) : "f"(v)); return r;
}
__device__ __forceinline__ void ffma2(u64 &d, u64 a, u64 b) {
    asm("fma.rn.f32x2 %0, %1, %2, %0;" : "+l"(d) : "l"(a), "l"(b));
}
__device__ __forceinline__ float2 unpack2(u64 v) {
    float2 r; asm("mov.b64 {%0, %1}, %2;" : "=f"(r.x), "=f"(r.y) : "l"(v)); return r;
}

// ---------------- CSR build ----------------
__global__ void zero_deg(int n) {
    int i = blockIdx.x * blockDim.x + threadIdx.x;
    if (i < n) g_deg[i] = 0;
}

__global__ void histo(const int* __restrict__ rows, int e) {
    int i = blockIdx.x * blockDim.x + threadIdx.x;
    if (i < e) atomicAdd(&g_deg[rows[i]], 1);
}

__global__ void scan_local(int n) {
    __shared__ int s[1024];
    int i = blockIdx.x * 1024 + threadIdx.x;
    int v = (i < n) ? g_deg[i] : 0;
    s[threadIdx.x] = v;
    __syncthreads();
    for (int off = 1; off < 1024; off <<= 1) {
        int t = (threadIdx.x >= off) ? s[threadIdx.x - off] : 0;
        __syncthreads();
        s[threadIdx.x] += t;
        __syncthreads();
    }
    if (i < n) g_rowptr[i] = s[threadIdx.x] - v;   // exclusive within block
    if (threadIdx.x == 1023) g_bsum[blockIdx.x] = s[1023];
}

// parallel exclusive scan of block sums (nb <= 128)
__global__ void scan_sums(int nb) {
    __shared__ int s[128];
    int t = threadIdx.x;
    int v = (t < nb) ? g_bsum[t] : 0;
    s[t] = v;
    __syncthreads();
    for (int off = 1; off < 128; off <<= 1) {
        int u = (t >= off) ? s[t - off] : 0;
        __syncthreads();
        s[t] += u;
        __syncthreads();
    }
    if (t < nb) g_bsum[t] = s[t] - v;  // exclusive
}

__global__ void add_off(int n, int e) {
    int i = blockIdx.x * blockDim.x + threadIdx.x;
    if (i < n) {
        int v = g_rowptr[i] + g_bsum[i >> 10];
        g_rowptr[i] = v;
        g_cursor[i] = v;
        g_dinv[i]   = rsqrtf((float)g_deg[i] + 1.0f);
    }
    if (i == 0) g_rowptr[n] = e;
}

__global__ void scatter_edges(const int* __restrict__ rows, const int* __restrict__ cols, int e) {
    int i = blockIdx.x * blockDim.x + threadIdx.x;
    if (i < e) {
        int r = rows[i];
        int c = cols[i];
        int p = atomicAdd(&g_cursor[r], 1);
        g_cols[p] = c;
        g_wgt[p]  = g_dinv[r] * g_dinv[c];
    }
}

// ---------------- SGEMM: g_h[M,128](fp16) = A[M,128] @ B[128,128], f32x2 inner ----
// BM=128, BN=128, BK=16, 256 threads, 8(m) x 4(f32x2 n-pairs) register tile
__global__ __launch_bounds__(256) void sgemm128(int a_sel, const float* __restrict__ Aext,
                                                const float* __restrict__ B, int M) {
    const float* __restrict__ A = (a_sel == 0) ? Aext : g_x1;

    __shared__ float As[16][128];
    __shared__ float Bs[16][128];

    int tid = threadIdx.x;
    int bm  = blockIdx.x * 128;
    int tx  = tid & 15;      // n-group (8 floats = 4 pairs)
    int ty  = tid >> 4;      // m-group

    u64 acc[8][4];
#pragma unroll
    for (int i = 0; i < 8; i++)
#pragma unroll
        for (int j = 0; j < 4; j++) acc[i][j] = 0ull;

    int a_m = tid >> 2;            // 0..63
    int a_k = (tid & 3) << 2;      // 0,4,8,12
    int b_k = tid >> 5;            // 0..7
    int b_n = (tid & 31) << 2;     // 0..124

    for (int k0 = 0; k0 < 128; k0 += 16) {
#pragma unroll
        for (int h2 = 0; h2 < 2; h2++) {
            int m  = a_m + h2 * 64;
            int gm = bm + m;
            if (gm >= M) gm = M - 1;            // clamp loads, stores are masked
            float4 v = *(const float4*)&A[(size_t)gm * 128 + k0 + a_k];
            As[a_k + 0][m] = v.x;
            As[a_k + 1][m] = v.y;
            As[a_k + 2][m] = v.z;
            As[a_k + 3][m] = v.w;
        }
#pragma unroll
        for (int h2 = 0; h2 < 2; h2++) {
            int k = b_k + h2 * 8;
            *(float4*)&Bs[k][b_n] = *(const float4*)&B[(size_t)(k0 + k) * 128 + b_n];
        }
        __syncthreads();
#pragma unroll
        for (int k = 0; k < 16; k++) {
            float a[8];
            *(float4*)(a)     = *(const float4*)&As[k][ty * 8];
            *(float4*)(a + 4) = *(const float4*)&As[k][ty * 8 + 4];
            ulonglong2 bl = *(const ulonglong2*)&Bs[k][tx * 8];      // (b0,b1),(b2,b3)
            ulonglong2 bh = *(const ulonglong2*)&Bs[k][tx * 8 + 4];  // (b4,b5),(b6,b7)
            u64 a2[8];
#pragma unroll
            for (int i = 0; i < 8; i++) a2[i] = pack2_dup(a[i]);
#pragma unroll
            for (int i = 0; i < 8; i++) {
                ffma2(acc[i][0], a2[i], bl.x);
                ffma2(acc[i][1], a2[i], bl.y);
                ffma2(acc[i][2], a2[i], bh.x);
                ffma2(acc[i][3], a2[i], bh.y);
            }
        }
        __syncthreads();
    }
#pragma unroll
    for (int i = 0; i < 8; i++) {
        int gm = bm + ty * 8 + i;
        if (gm < M) {
            union { __half2 h2[4]; uint4 v; } pk;
#pragma unroll
            for (int j = 0; j < 4; j++) {
                float2 f = unpack2(acc[i][j]);
                pk.h2[j] = __floats2half2_rn(f.x, f.y);
            }
            *(uint4*)&g_h[(size_t)gm * 128 + tx * 8] = pk.v;   // 8 halfs = 16B
        }
    }
}

// ---------------- gather aggregation + bias + BN + ReLU ----------------
// one warp per destination node; lane covers 4 channels (8B fp16 gather); unroll x4
__global__ void aggregate(const float* __restrict__ bias,
                          const float* __restrict__ gamma,
                          const float* __restrict__ beta,
                          const float* __restrict__ mean,
                          const float* __restrict__ var,
                          int dst_sel, int n) {
    int gw = (blockIdx.x * blockDim.x + threadIdx.x) >> 5;
    if (gw >= n) return;
    int lane = threadIdx.x & 31;
    int c0   = lane << 2;

    float di    = g_dinv[gw];
    int   start = g_rowptr[gw];
    int   end   = g_rowptr[gw + 1];

    float ax = 0.f, ay = 0.f, az = 0.f, aw = 0.f;
    int j = start;
    for (; j + 3 < end; j += 4) {
        int   c1 = g_cols[j],     c2 = g_cols[j + 1];
        int   c3 = g_cols[j + 2], c4 = g_cols[j + 3];
        float w1 = g_wgt[j],      w2 = g_wgt[j + 1];
        float w3 = g_wgt[j + 2],  w4 = g_wgt[j + 3];
        uint2 r1 = *(const uint2*)&g_h[(size_t)c1 * 128 + c0];
        uint2 r2 = *(const uint2*)&g_h[(size_t)c2 * 128 + c0];
        uint2 r3 = *(const uint2*)&g_h[(size_t)c3 * 128 + c0];
        uint2 r4 = *(const uint2*)&g_h[(size_t)c4 * 128 + c0];
        float2 a1 = __half22float2(*(__half2*)&r1.x), b1f = __half22float2(*(__half2*)&r1.y);
        float2 a2 = __half22float2(*(__half2*)&r2.x), b2f = __half22float2(*(__half2*)&r2.y);
        float2 a3 = __half22float2(*(__half2*)&r3.x), b3f = __half22float2(*(__half2*)&r3.y);
        float2 a4 = __half22float2(*(__half2*)&r4.x), b4f = __half22float2(*(__half2*)&r4.y);
        ax += a1.x * w1 + a2.x * w2 + a3.x * w3 + a4.x * w4;
        ay += a1.y * w1 + a2.y * w2 + a3.y * w3 + a4.y * w4;
        az += b1f.x * w1 + b2f.x * w2 + b3f.x * w3 + b4f.x * w4;
        aw += b1f.y * w1 + b2f.y * w2 + b3f.y * w3 + b4f.y * w4;
    }
    for (; j < end; j++) {
        int c1 = g_cols[j];
        float w1 = g_wgt[j];
        uint2 r1 = *(const uint2*)&g_h[(size_t)c1 * 128 + c0];
        float2 a1 = __half22float2(*(__half2*)&r1.x), b1f = __half22float2(*(__half2*)&r1.y);
        ax += a1.x * w1; ay += a1.y * w1; az += b1f.x * w1; aw += b1f.y * w1;
    }
    // self-loop
    {
        float ws = di * di;
        uint2 rs = *(const uint2*)&g_h[(size_t)gw * 128 + c0];
        float2 hs0 = __half22float2(*(__half2*)&rs.x), hs1 = __half22float2(*(__half2*)&rs.y);
        ax += hs0.x * ws; ay += hs0.y * ws; az += hs1.x * ws; aw += hs1.y * ws;
    }
    // epilogue: (agg + b - mean) * gamma*rsqrt(var+eps) + beta, then relu
    float4 bb = *(const float4*)&bias[c0];
    float4 gg = *(const float4*)&gamma[c0];
    float4 be = *(const float4*)&beta[c0];
    float4 mm = *(const float4*)&mean[c0];
    float4 vv = *(const float4*)&var[c0];

    float s0 = gg.x * rsqrtf(vv.x + 1e-5f);
    float s1 = gg.y * rsqrtf(vv.y + 1e-5f);
    float s2 = gg.z * rsqrtf(vv.z + 1e-5f);
    float s3 = gg.w * rsqrtf(vv.w + 1e-5f);

    float y0 = fmaxf((ax + bb.x - mm.x) * s0 + be.x, 0.0f);
    float y1 = fmaxf((ay + bb.y - mm.y) * s1 + be.y, 0.0f);
    float y2 = fmaxf((az + bb.z - mm.z) * s2 + be.z, 0.0f);
    float y3 = fmaxf((aw + bb.w - mm.w) * s3 + be.w, 0.0f);

    float* __restrict__ out = (dst_sel == 1) ? g_x1 : g_x2;
    *(float4*)&out[(size_t)gw * 128 + c0] = make_float4(y0, y1, y2, y3);
}

// ---------------- final FC: out = [x0 | x1 | x2] @ fc_W + fc_b, f32x2 inner ----------------
// block: 160 threads = 32 rows x 5 col-groups (8 cols = 4 pairs each). K = 3 x 128.
__global__ void fc_kernel(const float* __restrict__ x0,
                          const float* __restrict__ W,   // [384, 40] row-major
                          const float* __restrict__ bias,
                          float* __restrict__ out, int n) {
    __shared__ float Ws[128 * 40];   // 20 KB: one 128-row chunk of fc_W
    __shared__ float St[32 * 130];   // 16.25 KB: 32-row input tile, padded stride

    int tid = threadIdx.x;           // 0..159
    int r   = tid / 5;               // 0..31
    int cg  = (tid % 5) * 8;         // 0,8,16,24,32
    int row = blockIdx.x * 32 + r;

    u64 acc[4];
    {
        ulonglong2 b0 = *(const ulonglong2*)&bias[cg];
        ulonglong2 b1 = *(const ulonglong2*)&bias[cg + 4];
        acc[0] = b0.x; acc[1] = b0.y; acc[2] = b1.x; acc[3] = b1.y;
    }

    for (int s = 0; s < 3; s++) {
        const float* __restrict__ S = (s == 0) ? x0 : ((s == 1) ? g_x1 : g_x2);
        __syncthreads();
        // stage W chunk [128,40] for this source
        for (int i = tid; i < 1280; i += 160)
            ((float4*)Ws)[i] = ((const float4*)W)[s * 1280 + i];
        // stage input tile [32,128] with padded stride 130 (bank-conflict-free)
        for (int i = tid; i < 1024; i += 160) {
            int rr = i >> 5;
            int kk = (i & 31) << 2;
            int gr = blockIdx.x * 32 + rr;
            float4 v = (gr < n) ? *(const float4*)&S[(size_t)gr * 128 + kk]
                                : make_float4(0.f, 0.f, 0.f, 0.f);
            St[rr * 130 + kk + 0] = v.x;
            St[rr * 130 + kk + 1] = v.y;
            St[rr * 130 + kk + 2] = v.z;
            St[rr * 130 + kk + 3] = v.w;
        }
        __syncthreads();
#pragma unroll 4
        for (int k = 0; k < 128; k++) {
            u64 a2 = pack2_dup(St[r * 130 + k]);
            const float* wr = &Ws[k * 40 + cg];
            ulonglong2 w0 = *(const ulonglong2*)(wr);
            ulonglong2 w1 = *(const ulonglong2*)(wr + 4);
            ffma2(acc[0], a2, w0.x);
            ffma2(acc[1], a2, w0.y);
            ffma2(acc[2], a2, w1.x);
            ffma2(acc[3], a2, w1.y);
        }
    }
    if (row < n) {
        *(ulonglong2*)&out[(size_t)row * 40 + cg]     = make_ulonglong2(acc[0], acc[1]);
        *(ulonglong2*)&out[(size_t)row * 40 + cg + 4] = make_ulonglong2(acc[2], acc[3]);
    }
}

// ---------------- launch ----------------
extern "C" void kernel_launch(void* const* d_in, const int* in_sizes, int n_in,
                              void* d_out, int out_size) {
    const float* x   = (const float*)d_in[0];
    const int*   ei  = (const int*)  d_in[1];
    const float* W1  = (const float*)d_in[2];
    const float* b1  = (const float*)d_in[3];
    const float* W2  = (const float*)d_in[4];
    const float* b2  = (const float*)d_in[5];
    const float* g1  = (const float*)d_in[6];
    const float* be1 = (const float*)d_in[7];
    const float* m1  = (const float*)d_in[8];
    const float* v1  = (const float*)d_in[9];
    const float* g2  = (const float*)d_in[10];
    const float* be2 = (const float*)d_in[11];
    const float* m2  = (const float*)d_in[12];
    const float* v2  = (const float*)d_in[13];
    const float* fcW = (const float*)d_in[14];
    const float* fcb = (const float*)d_in[15];
    float* out = (float*)d_out;

    int N = in_sizes[0] / 128;
    int E = in_sizes[1] / 2;
    const int* rows = ei;
    const int* cols = ei + E;

    const int T = 256;
    int gblocks = (N + 127) / 128;
    int nb = (N + 1023) / 1024;

    // CSR build; sgemm layer-1 slotted at launch index 3 so ncu profiles it
    zero_deg<<<(N + T - 1) / T, T>>>(N);                    // 0
    histo<<<(E + T - 1) / T, T>>>(rows, E);                 // 1
    scan_local<<<nb, 1024>>>(N);                            // 2
    sgemm128<<<gblocks, 256>>>(0, x, W1, N);                // 3 (independent of CSR)
    scan_sums<<<1, 128>>>(nb);                              // 4
    add_off<<<(N + T - 1) / T, T>>>(N, E);                  // 5
    scatter_edges<<<(E + T - 1) / T, T>>>(rows, cols, E);   // 6

    // layer 1 aggregate
    aggregate<<<(N + 7) / 8, 256>>>(b1, g1, be1, m1, v1, 1, N);
    // layer 2
    sgemm128<<<gblocks, 256>>>(1, x, W2, N);
    aggregate<<<(N + 7) / 8, 256>>>(b2, g2, be2, m2, v2, 2, N);
    // final FC on concat
    fc_kernel<<<(N + 31) / 32, 160>>>(x, fcW, fcb, out, N);
}

// round 6
// speedup vs baseline: 1.1171x; 1.0240x over previous
#include <cuda_runtime.h>
#include <cuda_fp16.h>

#define NN 100000
#define EE 1600000
#define HH 128
#define OUTC 40

typedef unsigned long long u64;

// ---------------- static device scratch (allocation-free rule) ----------------
__device__ __half g_h [(size_t)NN * HH];  // xW (layer1 then layer2), fp16 storage
__device__ float  g_x1[(size_t)NN * HH];  // relu(bn1(gcn1))
__device__ float  g_x2[(size_t)NN * HH];  // relu(bn2(gcn2))
__device__ float  g_dinv[NN];
__device__ int    g_deg[NN];
__device__ int    g_rowptr[NN + 1];
__device__ int    g_cursor[NN];
__device__ int    g_cols[EE];
__device__ float  g_wgt[EE];
__device__ int    g_bsum[128];

// ---------------- f32x2 helpers (FFMA2 — only reachable via PTX) ----------------
__device__ __forceinline__ u64 pack2_dup(float v) {
    u64 r; asm("mov.b64 %0, {%1, %1};" : "=l"(r) : "f"(v)); return r;
}
__device__ __forceinline__ void ffma2(u64 &d, u64 a, u64 b) {
    asm("fma.rn.f32x2 %0, %1, %2, %0;" : "+l"(d) : "l"(a), "l"(b));
}
__device__ __forceinline__ float2 unpack2(u64 v) {
    float2 r; asm("mov.b64 {%0, %1}, %2;" : "=f"(r.x), "=f"(r.y) : "l"(v)); return r;
}

// ---------------- CSR build ----------------
__global__ void zero_deg(int n) {
    int i = blockIdx.x * blockDim.x + threadIdx.x;
    if (i < n) g_deg[i] = 0;
}

__global__ void histo(const int* __restrict__ rows, int e) {
    int i = blockIdx.x * blockDim.x + threadIdx.x;
    if (i < e) atomicAdd(&g_deg[rows[i]], 1);
}

__global__ void scan_local(int n) {
    __shared__ int s[1024];
    int i = blockIdx.x * 1024 + threadIdx.x;
    int v = (i < n) ? g_deg[i] : 0;
    s[threadIdx.x] = v;
    __syncthreads();
    for (int off = 1; off < 1024; off <<= 1) {
        int t = (threadIdx.x >= off) ? s[threadIdx.x - off] : 0;
        __syncthreads();
        s[threadIdx.x] += t;
        __syncthreads();
    }
    if (i < n) g_rowptr[i] = s[threadIdx.x] - v;   // exclusive within block
    if (threadIdx.x == 1023) g_bsum[blockIdx.x] = s[1023];
}

// parallel exclusive scan of block sums (nb <= 128)
__global__ void scan_sums(int nb) {
    __shared__ int s[128];
    int t = threadIdx.x;
    int v = (t < nb) ? g_bsum[t] : 0;
    s[t] = v;
    __syncthreads();
    for (int off = 1; off < 128; off <<= 1) {
        int u = (t >= off) ? s[t - off] : 0;
        __syncthreads();
        s[t] += u;
        __syncthreads();
    }
    if (t < nb) g_bsum[t] = s[t] - v;  // exclusive
}

__global__ void add_off(int n, int e) {
    int i = blockIdx.x * blockDim.x + threadIdx.x;
    if (i < n) {
        int v = g_rowptr[i] + g_bsum[i >> 10];
        g_rowptr[i] = v;
        g_cursor[i] = v;
        g_dinv[i]   = rsqrtf((float)g_deg[i] + 1.0f);
    }
    if (i == 0) g_rowptr[n] = e;
}

__global__ void scatter_edges(const int* __restrict__ rows, const int* __restrict__ cols, int e) {
    int i = blockIdx.x * blockDim.x + threadIdx.x;
    if (i < e) {
        int r = rows[i];
        int c = cols[i];
        int p = atomicAdd(&g_cursor[r], 1);
        g_cols[p] = c;
        g_wgt[p]  = g_dinv[r] * g_dinv[c];
    }
}

// ---------------- SGEMM: g_h[M,128](fp16) = A[M,128] @ B[128,128] ----------------
// BM=128, BN=128, BK=16, 256 threads, 8(m) x 4(f32x2 n-pairs) tile, double-buffered
__global__ __launch_bounds__(256, 2) void sgemm128(int a_sel, const float* __restrict__ Aext,
                                                   const float* __restrict__ B, int M) {
    const float* __restrict__ A = (a_sel == 0) ? Aext : g_x1;

    __shared__ float As[2][16][128];
    __shared__ float Bs[2][16][128];

    int tid = threadIdx.x;
    int bm  = blockIdx.x * 128;
    int tx  = tid & 15;      // n-group (8 floats = 4 pairs)
    int ty  = tid >> 4;      // m-group

    u64 acc[8][4];
#pragma unroll
    for (int i = 0; i < 8; i++)
#pragma unroll
        for (int j = 0; j < 4; j++) acc[i][j] = 0ull;

    int a_m = tid >> 2;            // 0..63
    int a_k = (tid & 3) << 2;      // 0,4,8,12
    int b_k = tid >> 5;            // 0..7
    int b_n = (tid & 31) << 2;     // 0..124

    int gm0 = bm + a_m;       if (gm0 >= M) gm0 = M - 1;
    int gm1 = bm + a_m + 64;  if (gm1 >= M) gm1 = M - 1;

    // preload tile 0
    {
        float4 v0 = *(const float4*)&A[(size_t)gm0 * 128 + a_k];
        float4 v1 = *(const float4*)&A[(size_t)gm1 * 128 + a_k];
        As[0][a_k + 0][a_m]      = v0.x;
        As[0][a_k + 1][a_m]      = v0.y;
        As[0][a_k + 2][a_m]      = v0.z;
        As[0][a_k + 3][a_m]      = v0.w;
        As[0][a_k + 0][a_m + 64] = v1.x;
        As[0][a_k + 1][a_m + 64] = v1.y;
        As[0][a_k + 2][a_m + 64] = v1.z;
        As[0][a_k + 3][a_m + 64] = v1.w;
        *(float4*)&Bs[0][b_k][b_n]     = *(const float4*)&B[(size_t)b_k * 128 + b_n];
        *(float4*)&Bs[0][b_k + 8][b_n] = *(const float4*)&B[(size_t)(b_k + 8) * 128 + b_n];
    }
    __syncthreads();

#pragma unroll
    for (int k0 = 0; k0 < 8; k0++) {
        int cur = k0 & 1;
        float4 pa0, pa1, pb0, pb1;
        if (k0 < 7) {
            int kk = (k0 + 1) * 16;
            pa0 = *(const float4*)&A[(size_t)gm0 * 128 + kk + a_k];
            pa1 = *(const float4*)&A[(size_t)gm1 * 128 + kk + a_k];
            pb0 = *(const float4*)&B[(size_t)(kk + b_k) * 128 + b_n];
            pb1 = *(const float4*)&B[(size_t)(kk + b_k + 8) * 128 + b_n];
        }
#pragma unroll
        for (int k = 0; k < 16; k++) {
            float a[8];
            *(float4*)(a)     = *(const float4*)&As[cur][k][ty * 8];
            *(float4*)(a + 4) = *(const float4*)&As[cur][k][ty * 8 + 4];
            ulonglong2 bl = *(const ulonglong2*)&Bs[cur][k][tx * 8];
            ulonglong2 bh = *(const ulonglong2*)&Bs[cur][k][tx * 8 + 4];
            u64 a2[8];
#pragma unroll
            for (int i = 0; i < 8; i++) a2[i] = pack2_dup(a[i]);
#pragma unroll
            for (int i = 0; i < 8; i++) {
                ffma2(acc[i][0], a2[i], bl.x);
                ffma2(acc[i][1], a2[i], bl.y);
                ffma2(acc[i][2], a2[i], bh.x);
                ffma2(acc[i][3], a2[i], bh.y);
            }
        }
        if (k0 < 7) {
            int nxt = cur ^ 1;
            As[nxt][a_k + 0][a_m]      = pa0.x;
            As[nxt][a_k + 1][a_m]      = pa0.y;
            As[nxt][a_k + 2][a_m]      = pa0.z;
            As[nxt][a_k + 3][a_m]      = pa0.w;
            As[nxt][a_k + 0][a_m + 64] = pa1.x;
            As[nxt][a_k + 1][a_m + 64] = pa1.y;
            As[nxt][a_k + 2][a_m + 64] = pa1.z;
            As[nxt][a_k + 3][a_m + 64] = pa1.w;
            *(float4*)&Bs[nxt][b_k][b_n]     = pb0;
            *(float4*)&Bs[nxt][b_k + 8][b_n] = pb1;
            __syncthreads();
        }
    }

#pragma unroll
    for (int i = 0; i < 8; i++) {
        int gm = bm + ty * 8 + i;
        if (gm < M) {
            union { __half2 h2[4]; uint4 v; } pk;
#pragma unroll
            for (int j = 0; j < 4; j++) {
                float2 f = unpack2(acc[i][j]);
                pk.h2[j] = __floats2half2_rn(f.x, f.y);
            }
            *(uint4*)&g_h[(size_t)gm * 128 + tx * 8] = pk.v;   // 8 halfs = 16B
        }
    }
}

// ---------------- gather aggregation + bias + BN + ReLU ----------------
// one HALF-WARP per destination node; each lane covers 8 fp16 channels (16B LDG)
__global__ void aggregate(const float* __restrict__ bias,
                          const float* __restrict__ gamma,
                          const float* __restrict__ beta,
                          const float* __restrict__ mean,
                          const float* __restrict__ var,
                          int dst_sel, int n) {
    int node = (blockIdx.x * blockDim.x + threadIdx.x) >> 4;
    if (node >= n) return;
    int lane = threadIdx.x & 15;
    int c0   = lane << 3;                 // 8 channels = 16 bytes fp16

    float di    = g_dinv[node];
    int   start = g_rowptr[node];
    int   end   = g_rowptr[node + 1];

    float acc[8];
#pragma unroll
    for (int q = 0; q < 8; q++) acc[q] = 0.f;

    int j = start;
    for (; j + 3 < end; j += 4) {
        int   cA = g_cols[j],     cB = g_cols[j + 1];
        int   cC = g_cols[j + 2], cD = g_cols[j + 3];
        float wA = g_wgt[j],      wB = g_wgt[j + 1];
        float wC = g_wgt[j + 2],  wD = g_wgt[j + 3];
        uint4 rA = *(const uint4*)&g_h[(size_t)cA * 128 + c0];
        uint4 rB = *(const uint4*)&g_h[(size_t)cB * 128 + c0];
        uint4 rC = *(const uint4*)&g_h[(size_t)cC * 128 + c0];
        uint4 rD = *(const uint4*)&g_h[(size_t)cD * 128 + c0];
#pragma unroll
        for (int q = 0; q < 4; q++) {
            float2 fA = __half22float2(((const __half2*)&rA)[q]);
            float2 fB = __half22float2(((const __half2*)&rB)[q]);
            float2 fC = __half22float2(((const __half2*)&rC)[q]);
            float2 fD = __half22float2(((const __half2*)&rD)[q]);
            acc[2 * q]     += fA.x * wA + fB.x * wB + fC.x * wC + fD.x * wD;
            acc[2 * q + 1] += fA.y * wA + fB.y * wB + fC.y * wC + fD.y * wD;
        }
    }
    for (; j < end; j++) {
        int   cA = g_cols[j];
        float wA = g_wgt[j];
        uint4 rA = *(const uint4*)&g_h[(size_t)cA * 128 + c0];
#pragma unroll
        for (int q = 0; q < 4; q++) {
            float2 fA = __half22float2(((const __half2*)&rA)[q]);
            acc[2 * q]     += fA.x * wA;
            acc[2 * q + 1] += fA.y * wA;
        }
    }
    // self-loop
    {
        float ws = di * di;
        uint4 rs = *(const uint4*)&g_h[(size_t)node * 128 + c0];
#pragma unroll
        for (int q = 0; q < 4; q++) {
            float2 fs = __half22float2(((const __half2*)&rs)[q]);
            acc[2 * q]     += fs.x * ws;
            acc[2 * q + 1] += fs.y * ws;
        }
    }

    // epilogue: (agg + b - mean) * gamma*rsqrt(var+eps) + beta, then relu
    float* __restrict__ out = (dst_sel == 1) ? g_x1 : g_x2;
#pragma unroll
    for (int h = 0; h < 2; h++) {
        int c = c0 + h * 4;
        float4 bb = *(const float4*)&bias[c];
        float4 gg = *(const float4*)&gamma[c];
        float4 be = *(const float4*)&beta[c];
        float4 mm = *(const float4*)&mean[c];
        float4 vv = *(const float4*)&var[c];
        float s0 = gg.x * rsqrtf(vv.x + 1e-5f);
        float s1 = gg.y * rsqrtf(vv.y + 1e-5f);
        float s2 = gg.z * rsqrtf(vv.z + 1e-5f);
        float s3 = gg.w * rsqrtf(vv.w + 1e-5f);
        float y0 = fmaxf((acc[4 * h + 0] + bb.x - mm.x) * s0 + be.x, 0.0f);
        float y1 = fmaxf((acc[4 * h + 1] + bb.y - mm.y) * s1 + be.y, 0.0f);
        float y2 = fmaxf((acc[4 * h + 2] + bb.z - mm.z) * s2 + be.z, 0.0f);
        float y3 = fmaxf((acc[4 * h + 3] + bb.w - mm.w) * s3 + be.w, 0.0f);
        *(float4*)&out[(size_t)node * 128 + c] = make_float4(y0, y1, y2, y3);
    }
}

// ---------------- final FC: out = [x0 | x1 | x2] @ fc_W + fc_b, f32x2 inner ----------------
// block: 160 threads = 32 rows x 5 col-groups (8 cols = 4 pairs each). K = 3 x 128.
__global__ void fc_kernel(const float* __restrict__ x0,
                          const float* __restrict__ W,   // [384, 40] row-major
                          const float* __restrict__ bias,
                          float* __restrict__ out, int n) {
    __shared__ float Ws[128 * 40];   // 20 KB: one 128-row chunk of fc_W
    __shared__ float St[32 * 130];   // 16.25 KB: 32-row input tile, padded stride

    int tid = threadIdx.x;           // 0..159
    int r   = tid / 5;               // 0..31
    int cg  = (tid % 5) * 8;         // 0,8,16,24,32
    int row = blockIdx.x * 32 + r;

    u64 acc[4];
    {
        ulonglong2 b0 = *(const ulonglong2*)&bias[cg];
        ulonglong2 b1 = *(const ulonglong2*)&bias[cg + 4];
        acc[0] = b0.x; acc[1] = b0.y; acc[2] = b1.x; acc[3] = b1.y;
    }

    for (int s = 0; s < 3; s++) {
        const float* __restrict__ S = (s == 0) ? x0 : ((s == 1) ? g_x1 : g_x2);
        __syncthreads();
        // stage W chunk [128,40] for this source
        for (int i = tid; i < 1280; i += 160)
            ((float4*)Ws)[i] = ((const float4*)W)[s * 1280 + i];
        // stage input tile [32,128] with padded stride 130 (bank-conflict-free)
        for (int i = tid; i < 1024; i += 160) {
            int rr = i >> 5;
            int kk = (i & 31) << 2;
            int gr = blockIdx.x * 32 + rr;
            float4 v = (gr < n) ? *(const float4*)&S[(size_t)gr * 128 + kk]
                                : make_float4(0.f, 0.f, 0.f, 0.f);
            St[rr * 130 + kk + 0] = v.x;
            St[rr * 130 + kk + 1] = v.y;
            St[rr * 130 + kk + 2] = v.z;
            St[rr * 130 + kk + 3] = v.w;
        }
        __syncthreads();
#pragma unroll 4
        for (int k = 0; k < 128; k++) {
            u64 a2 = pack2_dup(St[r * 130 + k]);
            const float* wr = &Ws[k * 40 + cg];
            ulonglong2 w0 = *(const ulonglong2*)(wr);
            ulonglong2 w1 = *(const ulonglong2*)(wr + 4);
            ffma2(acc[0], a2, w0.x);
            ffma2(acc[1], a2, w0.y);
            ffma2(acc[2], a2, w1.x);
            ffma2(acc[3], a2, w1.y);
        }
    }
    if (row < n) {
        *(ulonglong2*)&out[(size_t)row * 40 + cg]     = make_ulonglong2(acc[0], acc[1]);
        *(ulonglong2*)&out[(size_t)row * 40 + cg + 4] = make_ulonglong2(acc[2], acc[3]);
    }
}

// ---------------- launch ----------------
extern "C" void kernel_launch(void* const* d_in, const int* in_sizes, int n_in,
                              void* d_out, int out_size) {
    const float* x   = (const float*)d_in[0];
    const int*   ei  = (const int*)  d_in[1];
    const float* W1  = (const float*)d_in[2];
    const float* b1  = (const float*)d_in[3];
    const float* W2  = (const float*)d_in[4];
    const float* b2  = (const float*)d_in[5];
    const float* g1  = (const float*)d_in[6];
    const float* be1 = (const float*)d_in[7];
    const float* m1  = (const float*)d_in[8];
    const float* v1  = (const float*)d_in[9];
    const float* g2  = (const float*)d_in[10];
    const float* be2 = (const float*)d_in[11];
    const float* m2  = (const float*)d_in[12];
    const float* v2  = (const float*)d_in[13];
    const float* fcW = (const float*)d_in[14];
    const float* fcb = (const float*)d_in[15];
    float* out = (float*)d_out;

    int N = in_sizes[0] / 128;
    int E = in_sizes[1] / 2;
    const int* rows = ei;
    const int* cols = ei + E;

    const int T = 256;
    int gblocks = (N + 127) / 128;
    int nb = (N + 1023) / 1024;

    // CSR build; sgemm layer-1 interleaved (independent of CSR)
    zero_deg<<<(N + T - 1) / T, T>>>(N);                    // 0
    histo<<<(E + T - 1) / T, T>>>(rows, E);                 // 1
    scan_local<<<nb, 1024>>>(N);                            // 2
    sgemm128<<<gblocks, 256>>>(0, x, W1, N);                // 3
    scan_sums<<<1, 128>>>(nb);                              // 4
    add_off<<<(N + T - 1) / T, T>>>(N, E);                  // 5
    scatter_edges<<<(E + T - 1) / T, T>>>(rows, cols, E);   // 6

    // layer 1 aggregate (16 threads per node)
    aggregate<<<(N + 15) / 16, 256>>>(b1, g1, be1, m1, v1, 1, N);
    // layer 2
    sgemm128<<<gblocks, 256>>>(1, x, W2, N);
    aggregate<<<(N + 15) / 16, 256>>>(b2, g2, be2, m2, v2, 2, N);
    // final FC on concat
    fc_kernel<<<(N + 31) / 32, 160>>>(x, fcW, fcb, out, N);
}